// round 11
// baseline (speedup 1.0000x reference)
#include <cuda_runtime.h>
#include <cuda_fp16.h>
#include <cstdint>

// ---------------- problem constants ----------------
#define VOCAB 50000
#define EMB   1024
#define HID   2048
#define BATCH 256
#define SEQ   128
#define NG    6144   // packed gate cols: band b=0..127 of 16 j's, within band: i(16) g(16) o(16)

// ---------------- GEMM tiling ----------------
#define TM 128
#define TN 96
#define DEPTH 4
#define STAGE_A (128*128)              // 16384 B
#define STAGE_B (96*128)               // 12288 B
#define STAGE_BYTES (STAGE_A+STAGE_B)  // 28672 B
#define GEMM_SMEM (DEPTH*STAGE_BYTES)  // 114688 B
#define GTILE_PITCH_B 272              // 128 halfs (256B) + 16B pad
#define GTILE_BYTES (96*GTILE_PITCH_B) // 26112 B
#define SNAP_OFF (GEMM_SMEM + GTILE_BYTES)     // 140800
#define RECUR_SMEM (SNAP_OFF + 4*256)          // + snapshot ring (4 x 64 ints) = 141824

// packed col n -> original weight row:
//   band = n/48, w = n%48, gate = w>>4, jj = w&15, j = band*16+jj
//   wr = j + (gate==0 ? 0 : gate==1 ? 4096 : 6144)   (i, g, o; f-gate unused)

// ---------------- scratch (__device__ globals) ----------------
__device__ __half g_Xemb[(size_t)BATCH * SEQ * EMB];   // fp16 embeddings, K-major
__device__ __half g_G[(size_t)SEQ * NG * BATCH];       // precomputed gates fp16, layout [t][n][b]
__device__ __half g_Whh[(size_t)NG * HID];             // packed fp16 weights
__device__ __half g_Wib[(size_t)NG * EMB];
__device__ __half g_Wif[(size_t)NG * EMB];
__device__ float  g_bb[NG];
__device__ float  g_bf[NG];
__device__ __half g_H[2][(size_t)BATCH * HID];         // h ping-pong fp16
__device__ int    g_flag[SEQ][2][64];                  // per (step, x-group, producer-y) flags

// ---------------- helpers ----------------
__device__ __forceinline__ uint32_t smem_u32(const void* p) {
    uint32_t a;
    asm("{ .reg .u64 t; cvta.to.shared.u64 t, %1; cvt.u32.u64 %0, t; }" : "=r"(a) : "l"(p));
    return a;
}

#define CP16(saddr, gptr) \
    asm volatile("cp.async.cg.shared.global [%0], [%1], 16;" :: "r"(saddr), "l"(gptr))

#define LDSM4(r, a) \
    asm volatile("ldmatrix.sync.aligned.m8n8.x4.shared.b16 {%0,%1,%2,%3}, [%4];" \
        : "=r"((r)[0]), "=r"((r)[1]), "=r"((r)[2]), "=r"((r)[3]) : "r"(a))

// fp16-accumulator mma: probe for double-rate HMMA.16816.F16
__device__ __forceinline__ void mma_h(uint32_t c[2], const uint32_t a[4],
                                      uint32_t b0, uint32_t b1) {
    asm volatile(
        "mma.sync.aligned.m16n8k16.row.col.f16.f16.f16.f16 "
        "{%0,%1},{%2,%3,%4,%5},{%6,%7},{%0,%1};"
        : "+r"(c[0]), "+r"(c[1])
        : "r"(a[0]), "r"(a[1]), "r"(a[2]), "r"(a[3]), "r"(b0), "r"(b1));
}

__device__ __forceinline__ void unp(float acc[4], const uint32_t h[2]) {
    float2 lo = __half22float2(*(const __half2*)&h[0]);
    float2 hi = __half22float2(*(const __half2*)&h[1]);
    acc[0] += lo.x; acc[1] += lo.y; acc[2] += hi.x; acc[3] += hi.y;
}

__device__ __forceinline__ float sigm(float x)  { return 1.f / (1.f + __expf(-x)); }
__device__ __forceinline__ float tanhe(float x) { return 2.f / (1.f + __expf(-2.f * x)) - 1.f; }

__device__ __forceinline__ int gate_row(int n) {
    int band = n / 48, w = n - band * 48;
    int gate = w >> 4, jj = w & 15;
    return band * 16 + jj + (gate == 0 ? 0 : (gate == 1 ? 4096 : 6144));
}

// ---------------- prep kernels ----------------
__global__ void gather_embed(const int* __restrict__ idx, const float* __restrict__ table,
                             __half* __restrict__ dst) {
    int m = blockIdx.x;                 // m = t*256 + b
    int t = m >> 8, b = m & 255;
    int row = idx[b * SEQ + t];
    if ((unsigned)row >= (unsigned)VOCAB) row = 0;
    const float4* s = (const float4*)(table + (size_t)row * EMB) + threadIdx.x * 2;
    float4 v0 = s[0], v1 = s[1];
    __half2 h0 = __floats2half2_rn(v0.x, v0.y), h1 = __floats2half2_rn(v0.z, v0.w);
    __half2 h2 = __floats2half2_rn(v1.x, v1.y), h3 = __floats2half2_rn(v1.z, v1.w);
    uint4 o = make_uint4(*(uint32_t*)&h0, *(uint32_t*)&h1, *(uint32_t*)&h2, *(uint32_t*)&h3);
    ((uint4*)(dst + (size_t)m * EMB))[threadIdx.x] = o;
}

__global__ void pack_weight(__half* __restrict__ dst, const float* __restrict__ src, int K) {
    int n = blockIdx.x;
    int wr = gate_row(n);
    const float4* s = (const float4*)(src + (size_t)wr * K);
    uint4* d = (uint4*)(dst + (size_t)n * K);
    for (int i = threadIdx.x; i < (K >> 3); i += blockDim.x) {
        float4 a = s[i * 2], b = s[i * 2 + 1];
        __half2 h0 = __floats2half2_rn(a.x, a.y), h1 = __floats2half2_rn(a.z, a.w);
        __half2 h2 = __floats2half2_rn(b.x, b.y), h3 = __floats2half2_rn(b.z, b.w);
        d[i] = make_uint4(*(uint32_t*)&h0, *(uint32_t*)&h1, *(uint32_t*)&h2, *(uint32_t*)&h3);
    }
}

__global__ void pack_bias(float* __restrict__ db, const float* __restrict__ bi_b, const float* __restrict__ bh_b,
                          float* __restrict__ df, const float* __restrict__ bi_f, const float* __restrict__ bh_f) {
    int n = blockIdx.x * blockDim.x + threadIdx.x;
    if (n >= NG) return;
    int wr = gate_row(n);
    db[n] = bi_b[wr] + bh_b[wr];
    df[n] = bi_f[wr] + bh_f[wr];
}

__global__ void reset_flag() {
    ((int*)g_flag)[blockIdx.x * 256 + threadIdx.x] = 0;
}

// ---------------- fragments ----------------
struct Frag { uint32_t a0[4], a1[4], b0[4], b1[4], b2[4]; };

// 12-tile fp16-accum mma block for one ks step
#define MMA_BLOCK(c, h) do { \
    mma_h((h)[0][0], (c).a0, (c).b0[0], (c).b0[1]);  mma_h((h)[1][0], (c).a1, (c).b0[0], (c).b0[1]); \
    mma_h((h)[0][1], (c).a0, (c).b0[2], (c).b0[3]);  mma_h((h)[1][1], (c).a1, (c).b0[2], (c).b0[3]); \
    mma_h((h)[0][2], (c).a0, (c).b1[0], (c).b1[1]);  mma_h((h)[1][2], (c).a1, (c).b1[0], (c).b1[1]); \
    mma_h((h)[0][3], (c).a0, (c).b1[2], (c).b1[3]);  mma_h((h)[1][3], (c).a1, (c).b1[2], (c).b1[3]); \
    mma_h((h)[0][4], (c).a0, (c).b2[0], (c).b2[1]);  mma_h((h)[1][4], (c).a1, (c).b2[0], (c).b2[1]); \
    mma_h((h)[0][5], (c).a0, (c).b2[2], (c).b2[3]);  mma_h((h)[1][5], (c).a1, (c).b2[2], (c).b2[3]); \
} while (0)

// ---------------- one-shot GEMM (precompute / forward cell) ----------------
// mode 0: grid (n-panels, m-panels); writes fp16 G[t][n][b] = C + bias[n].
// mode 1: grid (m-panels, n-panels); register-local cell; fp32 h -> fout (ld=out_ld).
__global__ __launch_bounds__(256) void lstm_gemm(
    const __half* __restrict__ A, int K, const __half* __restrict__ W,
    const float* __restrict__ bias,
    __half* __restrict__ gout, float* __restrict__ fout,
    int mode, int out_ld)
{
    extern __shared__ char smem[];
    const uint32_t sbase = smem_u32(smem);
    const int tid = threadIdx.x;
    const int lane = tid & 31, warp = tid >> 5;
    const int gid = lane >> 2, tig = lane & 3;
    const int wm = warp & 3, wn = warp >> 2;
    const int bm = (mode == 0) ? blockIdx.y : blockIdx.x;
    const int bn = (mode == 0) ? blockIdx.x : blockIdx.y;
    const int m0 = bm * TM;
    const int j0 = bn * TN;

    float acc[2][6][4];
#pragma unroll
    for (int mt = 0; mt < 2; ++mt)
#pragma unroll
        for (int nt = 0; nt < 6; ++nt)
#pragma unroll
            for (int c = 0; c < 4; ++c) acc[mt][nt][c] = 0.f;

    const int ar = wm * 32 + (lane & 15);
    const uint32_t aoff0 = (uint32_t)ar * 128u, aoff1 = aoff0 + 2048u;
    const uint32_t aswz  = (uint32_t)(ar & 7) << 4;
    const uint32_t akh   = ((lane >> 4) & 1) << 4;
    const int brb = wn * 48 + (lane & 7) + ((lane >> 4) << 3);
    const uint32_t bswz = (uint32_t)(brb & 7) << 4;
    const uint32_t bkh  = ((lane >> 3) & 1) << 4;
    const uint32_t boff0 = (uint32_t)brb * 128u, boff1 = boff0 + 2048u, boff2 = boff0 + 4096u;

    const int nkt = K >> 6;
    const char* Abase = (const char*)A + (size_t)m0 * 2 * K;
    const char* Bbase = (const char*)W + (size_t)j0 * 2 * K;

    auto fill = [&](int kt) {
        uint32_t st = sbase + (uint32_t)(kt & 3) * STAGE_BYTES;
        const char* Ab = Abase + kt * 128;
        const char* Bb = Bbase + kt * 128;
#pragma unroll
        for (int i = 0; i < 4; ++i) {
            int s = tid + i * 256;
            int row = s >> 3, q = s & 7;
            CP16(st + (uint32_t)(row * 128) + (((uint32_t)(q * 16)) ^ ((uint32_t)(row & 7) << 4)),
                 Ab + (size_t)row * 2 * K + q * 16);
        }
        uint32_t stb = st + STAGE_A;
#pragma unroll
        for (int i = 0; i < 3; ++i) {
            int s = tid + i * 256;
            int row = s >> 3, q = s & 7;
            CP16(stb + (uint32_t)(row * 128) + (((uint32_t)(q * 16)) ^ ((uint32_t)(row & 7) << 4)),
                 Bb + (size_t)row * 2 * K + q * 16);
        }
    };

#pragma unroll
    for (int p = 0; p < DEPTH - 1; ++p) {
        if (p < nkt) fill(p);
        asm volatile("cp.async.commit_group;");
    }

    Frag f[2];
#pragma unroll 1
    for (int kt = 0; kt < nkt; ++kt) {
        asm volatile("cp.async.wait_group %0;" :: "n"(DEPTH - 2));
        __syncthreads();
        if (kt + DEPTH - 1 < nkt) fill(kt + DEPTH - 1);
        asm volatile("cp.async.commit_group;");

        uint32_t st  = sbase + (uint32_t)(kt & 3) * STAGE_BYTES;
        uint32_t stB = st + STAGE_A;
        {
            uint32_t ca = akh ^ aswz, cb = bkh ^ bswz;
            LDSM4(f[0].a0, st + aoff0 + ca);  LDSM4(f[0].a1, st + aoff1 + ca);
            LDSM4(f[0].b0, stB + boff0 + cb); LDSM4(f[0].b1, stB + boff1 + cb); LDSM4(f[0].b2, stB + boff2 + cb);
        }
        uint32_t hacc[2][6][2];
#pragma unroll
        for (int mt = 0; mt < 2; ++mt)
#pragma unroll
            for (int nt = 0; nt < 6; ++nt) { hacc[mt][nt][0] = 0u; hacc[mt][nt][1] = 0u; }
#pragma unroll
        for (int ks = 0; ks < 4; ++ks) {
            if (ks < 3) {
                int nb = (ks + 1) & 1;
                uint32_t ca = (((uint32_t)((ks + 1) * 32)) | akh) ^ aswz;
                uint32_t cb = (((uint32_t)((ks + 1) * 32)) | bkh) ^ bswz;
                LDSM4(f[nb].a0, st + aoff0 + ca);  LDSM4(f[nb].a1, st + aoff1 + ca);
                LDSM4(f[nb].b0, stB + boff0 + cb); LDSM4(f[nb].b1, stB + boff1 + cb); LDSM4(f[nb].b2, stB + boff2 + cb);
            }
            Frag& c = f[ks & 1];
            MMA_BLOCK(c, hacc);
        }
#pragma unroll
        for (int mt = 0; mt < 2; ++mt)
#pragma unroll
            for (int nt = 0; nt < 6; ++nt) unp(acc[mt][nt], hacc[mt][nt]);
    }

    if (mode == 0) {
        const int t = m0 >> 8;
        __half* Gt = gout + (size_t)t * ((size_t)NG * 256);
#pragma unroll
        for (int mt = 0; mt < 2; ++mt)
#pragma unroll
            for (int nt = 0; nt < 6; ++nt) {
                int b = (m0 + wm * 32 + mt * 16 + gid) & 255;
                int n = j0 + wn * 48 + nt * 8 + tig * 2;
                float bv0 = bias[n], bv1 = bias[n + 1];
                Gt[(size_t)n * 256 + b]           = __float2half(acc[mt][nt][0] + bv0);
                Gt[(size_t)(n + 1) * 256 + b]     = __float2half(acc[mt][nt][1] + bv1);
                Gt[(size_t)n * 256 + b + 8]       = __float2half(acc[mt][nt][2] + bv0);
                Gt[(size_t)(n + 1) * 256 + b + 8] = __float2half(acc[mt][nt][3] + bv1);
            }
    } else {
        // register-local cell: acc[mt][jh]=i, acc[mt][2+jh]=g, acc[mt][4+jh]=o
#pragma unroll
        for (int mt = 0; mt < 2; ++mt)
#pragma unroll
            for (int jh = 0; jh < 2; ++jh)
#pragma unroll
                for (int rp = 0; rp < 2; ++rp) {
                    int row = m0 + wm * 32 + mt * 16 + gid + rp * 8;
                    int nb = j0 + wn * 48 + jh * 8 + tig * 2;
                    float hv[2];
#pragma unroll
                    for (int col = 0; col < 2; ++col) {
                        float gi = acc[mt][jh][rp * 2 + col]     + bias[nb + col];
                        float gg = acc[mt][2 + jh][rp * 2 + col] + bias[nb + 16 + col];
                        float go = acc[mt][4 + jh][rp * 2 + col] + bias[nb + 32 + col];
                        hv[col] = sigm(go) * tanhe(sigm(gi) * tanhe(gg));
                    }
                    int j = bn * 32 + wn * 16 + jh * 8 + tig * 2;
                    *(float2*)&fout[(size_t)row * out_ld + j] = make_float2(hv[0], hv[1]);
                }
    }
}

// ---------------- persistent recurrence kernel ----------------
// 128 CTAs (grid 2x64), 1/SM. Fine-grained producer gating via cp.async flag
// snapshots (R9 structure); fp16-accum mma with per-k-tile fp32 promotion.
__global__ __launch_bounds__(256, 1) void lstm_recur(
    const __half* __restrict__ Gall, const __half* __restrict__ W,
    __half* __restrict__ H0, __half* __restrict__ H1, float* __restrict__ out)
{
    extern __shared__ char smem[];
    const uint32_t sbase = smem_u32(smem);
    const uint32_t gsm = sbase + GEMM_SMEM;
    __half* GsmH = (__half*)(smem + GEMM_SMEM);
    const uint32_t snap_base = sbase + SNAP_OFF;
    const int* snapI = (const int*)(smem + SNAP_OFF);
    const int tid = threadIdx.x;
    const int lane = tid & 31, warp = tid >> 5;
    const int gid = lane >> 2, tig = lane & 3;
    const int wm = warp & 3, wn = warp >> 2;
    const int x = blockIdx.x, y = blockIdx.y;
    const int m0 = x * TM, j0 = y * TN;

    const int ar = wm * 32 + (lane & 15);
    const uint32_t aoff0 = (uint32_t)ar * 128u, aoff1 = aoff0 + 2048u;
    const uint32_t aswz  = (uint32_t)(ar & 7) << 4;
    const uint32_t akh   = ((lane >> 4) & 1) << 4;
    const int brb = wn * 48 + (lane & 7) + ((lane >> 4) << 3);
    const uint32_t bswz = (uint32_t)(brb & 7) << 4;
    const uint32_t bkh  = ((lane >> 3) & 1) << 4;
    const uint32_t boff0 = (uint32_t)brb * 128u, boff1 = boff0 + 2048u, boff2 = boff0 + 4096u;

    const char* Bbase = (const char*)W + (size_t)j0 * 2 * HID;

#pragma unroll 1
    for (int s = 0; s < SEQ; ++s) {
        const int t = (SEQ - 1) - s;

        // group 0: G tile + (s>0) W stages 0..2 — all h-independent
        {
            const char* Gt = (const char*)(Gall + ((size_t)t * NG + j0) * 256 + m0);
#pragma unroll
            for (int i = 0; i < 6; ++i) {
                int sl = tid + i * 256;
                int r = sl >> 4, q = sl & 15;
                CP16(gsm + (uint32_t)(r * GTILE_PITCH_B + q * 16), Gt + (size_t)r * 512 + q * 16);
            }
        }
        if (s > 0) {
#pragma unroll
            for (int st_ = 0; st_ < 3; ++st_) {
                uint32_t sb = sbase + (uint32_t)st_ * STAGE_BYTES + STAGE_A;
                const char* Bb = Bbase + st_ * 128;
#pragma unroll
                for (int i = 0; i < 3; ++i) {
                    int sl = tid + i * 256;
                    int row = sl >> 3, q = sl & 7;
                    CP16(sb + (uint32_t)(row * 128) + (((uint32_t)(q * 16)) ^ ((uint32_t)(row & 7) << 4)),
                         Bb + (size_t)row * 2 * HID + q * 16);
                }
            }
        }
        asm volatile("cp.async.commit_group;");

        float acc[2][6][4];
#pragma unroll
        for (int mt = 0; mt < 2; ++mt)
#pragma unroll
            for (int nt = 0; nt < 6; ++nt)
#pragma unroll
                for (int c = 0; c < 4; ++c) acc[mt][nt][c] = 0.f;

        if (s > 0) {
            const int* flg = &g_flag[s - 1][x][0];

            // gate only on producers y0..5 (needed by prologue stages 0..2)
            {
                int not_ready;
                do {
                    int v = 1;
                    if (tid < 6)
                        asm volatile("ld.acquire.gpu.global.b32 %0, [%1];"
                                     : "=r"(v) : "l"(flg + tid) : "memory");
                    not_ready = __syncthreads_count(v == 0);
                } while (not_ready != 0);
            }

            const __half* Ap = ((s + 1) & 1) ? H1 : H0;
            const char* Abase = (const char*)Ap + (size_t)m0 * 2 * HID;

            auto fillA = [&](int kt) {
                uint32_t sa = sbase + (uint32_t)(kt & 3) * STAGE_BYTES;
                const char* Ab = Abase + kt * 128;
#pragma unroll
                for (int i = 0; i < 4; ++i) {
                    int sl = tid + i * 256;
                    int row = sl >> 3, q = sl & 7;
                    CP16(sa + (uint32_t)(row * 128) + (((uint32_t)(q * 16)) ^ ((uint32_t)(row & 7) << 4)),
                         Ab + (size_t)row * 2 * HID + q * 16);
                }
            };
            auto fillB = [&](int kt) {
                uint32_t sb = sbase + (uint32_t)(kt & 3) * STAGE_BYTES + STAGE_A;
                const char* Bb = Bbase + kt * 128;
#pragma unroll
                for (int i = 0; i < 3; ++i) {
                    int sl = tid + i * 256;
                    int row = sl >> 3, q = sl & 7;
                    CP16(sb + (uint32_t)(row * 128) + (((uint32_t)(q * 16)) ^ ((uint32_t)(row & 7) << 4)),
                         Bb + (size_t)row * 2 * HID + q * 16);
                }
            };

            // A prologue: snapshot (slot (j+4)&3) + fillA(j+3), j=-3..-1
#pragma unroll
            for (int j = -3; j < 0; ++j) {
                if (tid < 16)
                    CP16(snap_base + (uint32_t)(((j + 4) & 3) * 256 + tid * 16),
                         (const char*)flg + tid * 16);
                fillA(j + 3);
                asm volatile("cp.async.commit_group;");
            }

            Frag f[2];
#pragma unroll 1
            for (int kt = 0; kt < 32; ++kt) {
                asm volatile("cp.async.wait_group 2;");
                __syncthreads();

                // ---- compute stage kt ----
                uint32_t st  = sbase + (uint32_t)(kt & 3) * STAGE_BYTES;
                uint32_t stB = st + STAGE_A;
                {
                    uint32_t ca = akh ^ aswz, cb = bkh ^ bswz;
                    LDSM4(f[0].a0, st + aoff0 + ca);  LDSM4(f[0].a1, st + aoff1 + ca);
                    LDSM4(f[0].b0, stB + boff0 + cb); LDSM4(f[0].b1, stB + boff1 + cb); LDSM4(f[0].b2, stB + boff2 + cb);
                }
                uint32_t hacc[2][6][2];
#pragma unroll
                for (int mt = 0; mt < 2; ++mt)
#pragma unroll
                    for (int nt = 0; nt < 6; ++nt) { hacc[mt][nt][0] = 0u; hacc[mt][nt][1] = 0u; }
#pragma unroll
                for (int ks = 0; ks < 4; ++ks) {
                    if (ks < 3) {
                        int nb = (ks + 1) & 1;
                        uint32_t ca = (((uint32_t)((ks + 1) * 32)) | akh) ^ aswz;
                        uint32_t cb = (((uint32_t)((ks + 1) * 32)) | bkh) ^ bswz;
                        LDSM4(f[nb].a0, st + aoff0 + ca);  LDSM4(f[nb].a1, st + aoff1 + ca);
                        LDSM4(f[nb].b0, stB + boff0 + cb); LDSM4(f[nb].b1, stB + boff1 + cb); LDSM4(f[nb].b2, stB + boff2 + cb);
                    }
                    Frag& c = f[ks & 1];
                    MMA_BLOCK(c, hacc);
                }
#pragma unroll
                for (int mt = 0; mt < 2; ++mt)
#pragma unroll
                    for (int nt = 0; nt < 6; ++nt) unp(acc[mt][nt], hacc[mt][nt]);

                // ---- gate + refill stage kf = kt+3 ----
                int kf = kt + 3;
                if (kf < 32) {
                    int r0 = snapI[((kt + 1) & 3) * 64 + 2 * kf];
                    int r1 = snapI[((kt + 1) & 3) * 64 + 2 * kf + 1];
                    if (!(r0 && r1)) {                 // snapshot stale -> spin fallback
                        int not_ready;
                        do {
                            int v = 1;
                            if (tid < 2)
                                asm volatile("ld.acquire.gpu.global.b32 %0, [%1];"
                                             : "=r"(v) : "l"(flg + 2 * kf + tid) : "memory");
                            not_ready = __syncthreads_count(v == 0);
                        } while (not_ready != 0);
                    }
                    if (kt <= 25 && tid < 16)          // refresh snapshot (slot kt&3)
                        CP16(snap_base + (uint32_t)((kt & 3) * 256 + tid * 16),
                             (const char*)flg + tid * 16);
                    fillA(kf);
                    fillB(kf);
                }
                asm volatile("cp.async.commit_group;");
            }
        } else {
            asm volatile("cp.async.wait_group 0;");
            __syncthreads();
        }

        // ---- register-local cell epilogue (G addend from smem tile) ----
        __half* Hout = (s & 1) ? H1 : H0;
#pragma unroll
        for (int mt = 0; mt < 2; ++mt)
#pragma unroll
            for (int jh = 0; jh < 2; ++jh)
#pragma unroll
                for (int rp = 0; rp < 2; ++rp) {
                    int rl = wm * 32 + mt * 16 + gid + rp * 8;
                    int nb = wn * 48 + jh * 8 + tig * 2;
                    float hv[2];
#pragma unroll
                    for (int col = 0; col < 2; ++col) {
                        float gi = acc[mt][jh][rp * 2 + col]     + __half2float(GsmH[(nb + col) * 136 + rl]);
                        float gg = acc[mt][2 + jh][rp * 2 + col] + __half2float(GsmH[(nb + 16 + col) * 136 + rl]);
                        float go = acc[mt][4 + jh][rp * 2 + col] + __half2float(GsmH[(nb + 32 + col) * 136 + rl]);
                        hv[col] = sigm(go) * tanhe(sigm(gi) * tanhe(gg));
                    }
                    int j = y * 32 + wn * 16 + jh * 8 + tig * 2;
                    int row = m0 + rl;
                    if (s < SEQ - 1) {
                        *(__half2*)&Hout[(size_t)row * HID + j] = __floats2half2_rn(hv[0], hv[1]);
                    } else {
                        *(float2*)&out[(size_t)row * (2 * HID) + HID + j] = make_float2(hv[0], hv[1]);
                    }
                }
        __syncthreads();                 // GsmH reads + stage reads complete before next prefetch
        if (tid == 0 && s < SEQ - 1) {
            __threadfence();             // publish ALL warps' H stores at gpu scope
            asm volatile("st.release.gpu.global.b32 [%0], %1;"
                         :: "l"(&g_flag[s][x][y]), "r"(1) : "memory");
        }
    }
}

// ---------------- launch ----------------
extern "C" void kernel_launch(void* const* d_in, const int* in_sizes, int n_in,
                              void* d_out, int out_size) {
    const int*   inputs = (const int*)d_in[0];
    const float* table  = (const float*)d_in[1];
    const float* Wih_f  = (const float*)d_in[2];
    // d_in[3] = W_hh_f: mathematically unused (forward h = 0)
    const float* bih_f  = (const float*)d_in[4];
    const float* bhh_f  = (const float*)d_in[5];
    const float* Wih_b  = (const float*)d_in[6];
    const float* Whh_b  = (const float*)d_in[7];
    const float* bih_b  = (const float*)d_in[8];
    const float* bhh_b  = (const float*)d_in[9];
    float* out = (float*)d_out;

    __half *Xemb, *G, *Whh, *Wib, *Wif, *H;
    float *bb, *bf;
    cudaGetSymbolAddress((void**)&Xemb, g_Xemb);
    cudaGetSymbolAddress((void**)&G,    g_G);
    cudaGetSymbolAddress((void**)&Whh,  g_Whh);
    cudaGetSymbolAddress((void**)&Wib,  g_Wib);
    cudaGetSymbolAddress((void**)&Wif,  g_Wif);
    cudaGetSymbolAddress((void**)&bb,   g_bb);
    cudaGetSymbolAddress((void**)&bf,   g_bf);
    cudaGetSymbolAddress((void**)&H,    g_H);

    cudaFuncSetAttribute(lstm_gemm,  cudaFuncAttributeMaxDynamicSharedMemorySize, GEMM_SMEM);
    cudaFuncSetAttribute(lstm_recur, cudaFuncAttributeMaxDynamicSharedMemorySize, RECUR_SMEM);

    // prep
    gather_embed<<<BATCH * SEQ, 128>>>(inputs, table, Xemb);
    pack_weight<<<NG, 128>>>(Whh, Whh_b, HID);
    pack_weight<<<NG, 128>>>(Wib, Wih_b, EMB);
    pack_weight<<<NG, 128>>>(Wif, Wih_f, EMB);
    pack_bias<<<(NG + 255) / 256, 256>>>(bb, bih_b, bhh_b, bf, bih_f, bhh_f);
    reset_flag<<<SEQ * 2 * 64 / 256, 256>>>();

    // precompute G[t][n][b] (fp16); grid (n-panels, m-panels): waves share A tiles
    lstm_gemm<<<dim3(NG / TN, BATCH * SEQ / TM), 256, GEMM_SMEM>>>(
        Xemb, EMB, Wib, bb, G, nullptr, 0, 0);

    // forward direction: single cell on last timestep, h=c=0 -> out[:, 0:2048]
    lstm_gemm<<<dim3(BATCH / TM, NG / TN), 256, GEMM_SMEM>>>(
        Xemb + (size_t)(SEQ - 1) * BATCH * EMB, EMB, Wif, bf, nullptr, out, 1, 2 * HID);

    // backward recurrence: one persistent kernel, 128 resident CTAs
    lstm_recur<<<dim3(2, 64), 256, RECUR_SMEM>>>(
        G, Whh, H, H + (size_t)BATCH * HID, out);
}

// round 12
// speedup vs baseline: 1.1873x; 1.1873x over previous
#include <cuda_runtime.h>
#include <cuda_fp16.h>
#include <cstdint>

// ---------------- problem constants ----------------
#define VOCAB 50000
#define EMB   1024
#define HID   2048
#define BATCH 256
#define SEQ   128
#define NG    6144   // packed gate cols: band b=0..127 of 16 j's, within band: i(16) g(16) o(16)
#define NM    (BATCH*SEQ)   // 32768 (t,b) positions

// ---------------- GEMM tiling ----------------
#define TM 128
#define TN 96
#define DEPTH 4
#define STAGE_A (128*128)              // 16384 B
#define STAGE_B (96*128)               // 12288 B
#define STAGE_BYTES (STAGE_A+STAGE_B)  // 28672 B
#define GEMM_SMEM (DEPTH*STAGE_BYTES)  // 114688 B
#define GROW_B 208                     // G tile row pitch: 96 halfs (192B) + 16B pad
#define GROW_H 104
#define GTILE_BYTES (128*GROW_B)       // 26624 B
#define SNAP_OFF (GEMM_SMEM + GTILE_BYTES)     // 141312
#define RECUR_SMEM (SNAP_OFF + 4*256)          // 142336

// packed col n -> original weight row:
//   band = n/48, w = n%48, gate = w>>4, jj = w&15, j = band*16+jj
//   wr = j + (gate==0 ? 0 : gate==1 ? 4096 : 6144)   (i, g, o; f-gate unused)

// ---------------- scratch (__device__ globals) ----------------
__device__ __half g_Xu[(size_t)NM * EMB];        // fp16 embeddings per UNIQUE token
__device__ __half g_Xlast[(size_t)BATCH * EMB];  // fp16 embeddings, t = SEQ-1
__device__ __half g_Gu[(size_t)NM * NG];         // gates per unique token, row-major [u][n]
__device__ __half g_Whh[(size_t)NG * HID];       // packed fp16 weights
__device__ __half g_Wib[(size_t)NG * EMB];
__device__ __half g_Wif[(size_t)NG * EMB];
__device__ float  g_bb[NG];
__device__ float  g_bf[NG];
__device__ __half g_H[2][(size_t)BATCH * HID];   // h ping-pong fp16
__device__ int    g_flag[SEQ][2][64];            // per (step, x-group, producer-y) flags
__device__ int    g_mark[VOCAB];                 // token claimed?
__device__ int    g_uidmap[VOCAB];               // token -> uid
__device__ int    g_tok_of[NM];                  // uid -> token
__device__ int    g_uid_of[NM];                  // position m = t*256+b -> uid
__device__ int    g_nu;                          // number of unique tokens

// ---------------- helpers ----------------
__device__ __forceinline__ uint32_t smem_u32(const void* p) {
    uint32_t a;
    asm("{ .reg .u64 t; cvta.to.shared.u64 t, %1; cvt.u32.u64 %0, t; }" : "=r"(a) : "l"(p));
    return a;
}

#define CP16(saddr, gptr) \
    asm volatile("cp.async.cg.shared.global [%0], [%1], 16;" :: "r"(saddr), "l"(gptr))

#define LDSM4(r, a) \
    asm volatile("ldmatrix.sync.aligned.m8n8.x4.shared.b16 {%0,%1,%2,%3}, [%4];" \
        : "=r"((r)[0]), "=r"((r)[1]), "=r"((r)[2]), "=r"((r)[3]) : "r"(a))

__device__ __forceinline__ void mma_f16(float c[4], const uint32_t a[4],
                                        uint32_t b0, uint32_t b1) {
    asm volatile(
        "mma.sync.aligned.m16n8k16.row.col.f32.f16.f16.f32 "
        "{%0,%1,%2,%3},{%4,%5,%6,%7},{%8,%9},{%0,%1,%2,%3};"
        : "+f"(c[0]), "+f"(c[1]), "+f"(c[2]), "+f"(c[3])
        : "r"(a[0]), "r"(a[1]), "r"(a[2]), "r"(a[3]), "r"(b0), "r"(b1));
}

__device__ __forceinline__ float sigm(float x)  { return 1.f / (1.f + __expf(-x)); }
__device__ __forceinline__ float tanhe(float x) { return 2.f / (1.f + __expf(-2.f * x)) - 1.f; }

__device__ __forceinline__ int gate_row(int n) {
    int band = n / 48, w = n - band * 48;
    int gate = w >> 4, jj = w & 15;
    return band * 16 + jj + (gate == 0 ? 0 : (gate == 1 ? 4096 : 6144));
}

// ---------------- dedup kernels ----------------
__global__ void reset_all() {
    int i = blockIdx.x * 256 + threadIdx.x;
    if (i < VOCAB) g_mark[i] = 0;
    if (i < SEQ * 2 * 64) ((int*)g_flag)[i] = 0;
    if (i == 0) g_nu = 0;
}

__global__ void claim_tokens(const int* __restrict__ idx) {
    int m = blockIdx.x * 256 + threadIdx.x;   // m = t*256 + b
    int t = m >> 8, b = m & 255;
    int tok = idx[b * SEQ + t];
    if ((unsigned)tok >= (unsigned)VOCAB) tok = 0;
    if (atomicCAS(&g_mark[tok], 0, 1) == 0) {
        int u = atomicAdd(&g_nu, 1);
        g_uidmap[tok] = u;
        g_tok_of[u] = tok;
    }
}

__global__ void map_uid(const int* __restrict__ idx) {
    int m = blockIdx.x * 256 + threadIdx.x;
    int t = m >> 8, b = m & 255;
    int tok = idx[b * SEQ + t];
    if ((unsigned)tok >= (unsigned)VOCAB) tok = 0;
    g_uid_of[m] = g_uidmap[tok];
}

// copy one embedding row (fp32 -> fp16), 128 threads
__device__ __forceinline__ void copy_row_f2h(const float* __restrict__ src,
                                             __half* __restrict__ dst) {
    const float4* s = (const float4*)src + threadIdx.x * 2;
    float4 v0 = s[0], v1 = s[1];
    __half2 h0 = __floats2half2_rn(v0.x, v0.y), h1 = __floats2half2_rn(v0.z, v0.w);
    __half2 h2 = __floats2half2_rn(v1.x, v1.y), h3 = __floats2half2_rn(v1.z, v1.w);
    ((uint4*)dst)[threadIdx.x] =
        make_uint4(*(uint32_t*)&h0, *(uint32_t*)&h1, *(uint32_t*)&h2, *(uint32_t*)&h3);
}

__global__ void gather_unique(const float* __restrict__ table, __half* __restrict__ dst) {
    int u = blockIdx.x;
    if (u >= g_nu) return;
    copy_row_f2h(table + (size_t)g_tok_of[u] * EMB, dst + (size_t)u * EMB);
}

__global__ void gather_last(const int* __restrict__ idx, const float* __restrict__ table,
                            __half* __restrict__ dst) {
    int b = blockIdx.x;
    int row = idx[b * SEQ + (SEQ - 1)];
    if ((unsigned)row >= (unsigned)VOCAB) row = 0;
    copy_row_f2h(table + (size_t)row * EMB, dst + (size_t)b * EMB);
}

// ---------------- weight pack ----------------
__global__ void pack_weight(__half* __restrict__ dst, const float* __restrict__ src, int K) {
    int n = blockIdx.x;
    int wr = gate_row(n);
    const float4* s = (const float4*)(src + (size_t)wr * K);
    uint4* d = (uint4*)(dst + (size_t)n * K);
    for (int i = threadIdx.x; i < (K >> 3); i += blockDim.x) {
        float4 a = s[i * 2], b = s[i * 2 + 1];
        __half2 h0 = __floats2half2_rn(a.x, a.y), h1 = __floats2half2_rn(a.z, a.w);
        __half2 h2 = __floats2half2_rn(b.x, b.y), h3 = __floats2half2_rn(b.z, b.w);
        d[i] = make_uint4(*(uint32_t*)&h0, *(uint32_t*)&h1, *(uint32_t*)&h2, *(uint32_t*)&h3);
    }
}

__global__ void pack_bias(float* __restrict__ db, const float* __restrict__ bi_b, const float* __restrict__ bh_b,
                          float* __restrict__ df, const float* __restrict__ bi_f, const float* __restrict__ bh_f) {
    int n = blockIdx.x * blockDim.x + threadIdx.x;
    if (n >= NG) return;
    int wr = gate_row(n);
    db[n] = bi_b[wr] + bh_b[wr];
    df[n] = bi_f[wr] + bh_f[wr];
}

// ---------------- fragments ----------------
struct Frag { uint32_t a0[4], a1[4], b0[4], b1[4], b2[4]; };

// ---------------- one-shot GEMM (precompute / forward cell) ----------------
// mode 0: grid (n-panels, m-panels over unique rows); early-exits panels >= g_nu;
//         writes fp16 Gu[u][n] = C + bias[n] (row-major).
// mode 1: grid (m-panels, n-panels); register-local cell; fp32 h -> fout (ld=out_ld).
__global__ __launch_bounds__(256) void lstm_gemm(
    const __half* __restrict__ A, int K, const __half* __restrict__ W,
    const float* __restrict__ bias,
    __half* __restrict__ gout, float* __restrict__ fout,
    int mode, int out_ld)
{
    extern __shared__ char smem[];
    const uint32_t sbase = smem_u32(smem);
    const int tid = threadIdx.x;
    const int lane = tid & 31, warp = tid >> 5;
    const int gid = lane >> 2, tig = lane & 3;
    const int wm = warp & 3, wn = warp >> 2;
    const int bm = (mode == 0) ? blockIdx.y : blockIdx.x;
    const int bn = (mode == 0) ? blockIdx.x : blockIdx.y;
    const int m0 = bm * TM;
    const int j0 = bn * TN;

    if (mode == 0 && m0 >= g_nu) return;   // panel entirely beyond unique rows

    float acc[2][6][4];
#pragma unroll
    for (int mt = 0; mt < 2; ++mt)
#pragma unroll
        for (int nt = 0; nt < 6; ++nt)
#pragma unroll
            for (int c = 0; c < 4; ++c) acc[mt][nt][c] = 0.f;

    const int ar = wm * 32 + (lane & 15);
    const uint32_t aoff0 = (uint32_t)ar * 128u, aoff1 = aoff0 + 2048u;
    const uint32_t aswz  = (uint32_t)(ar & 7) << 4;
    const uint32_t akh   = ((lane >> 4) & 1) << 4;
    const int brb = wn * 48 + (lane & 7) + ((lane >> 4) << 3);
    const uint32_t bswz = (uint32_t)(brb & 7) << 4;
    const uint32_t bkh  = ((lane >> 3) & 1) << 4;
    const uint32_t boff0 = (uint32_t)brb * 128u, boff1 = boff0 + 2048u, boff2 = boff0 + 4096u;

    const int nkt = K >> 6;
    const char* Abase = (const char*)A + (size_t)m0 * 2 * K;
    const char* Bbase = (const char*)W + (size_t)j0 * 2 * K;

    auto fill = [&](int kt) {
        uint32_t st = sbase + (uint32_t)(kt & 3) * STAGE_BYTES;
        const char* Ab = Abase + kt * 128;
        const char* Bb = Bbase + kt * 128;
#pragma unroll
        for (int i = 0; i < 4; ++i) {
            int s = tid + i * 256;
            int row = s >> 3, q = s & 7;
            CP16(st + (uint32_t)(row * 128) + (((uint32_t)(q * 16)) ^ ((uint32_t)(row & 7) << 4)),
                 Ab + (size_t)row * 2 * K + q * 16);
        }
        uint32_t stb = st + STAGE_A;
#pragma unroll
        for (int i = 0; i < 3; ++i) {
            int s = tid + i * 256;
            int row = s >> 3, q = s & 7;
            CP16(stb + (uint32_t)(row * 128) + (((uint32_t)(q * 16)) ^ ((uint32_t)(row & 7) << 4)),
                 Bb + (size_t)row * 2 * K + q * 16);
        }
    };

#pragma unroll
    for (int p = 0; p < DEPTH - 1; ++p) {
        if (p < nkt) fill(p);
        asm volatile("cp.async.commit_group;");
    }

    Frag f[2];
#pragma unroll 1
    for (int kt = 0; kt < nkt; ++kt) {
        asm volatile("cp.async.wait_group %0;" :: "n"(DEPTH - 2));
        __syncthreads();
        if (kt + DEPTH - 1 < nkt) fill(kt + DEPTH - 1);
        asm volatile("cp.async.commit_group;");

        uint32_t st  = sbase + (uint32_t)(kt & 3) * STAGE_BYTES;
        uint32_t stB = st + STAGE_A;
        {
            uint32_t ca = akh ^ aswz, cb = bkh ^ bswz;
            LDSM4(f[0].a0, st + aoff0 + ca);  LDSM4(f[0].a1, st + aoff1 + ca);
            LDSM4(f[0].b0, stB + boff0 + cb); LDSM4(f[0].b1, stB + boff1 + cb); LDSM4(f[0].b2, stB + boff2 + cb);
        }
#pragma unroll
        for (int ks = 0; ks < 4; ++ks) {
            if (ks < 3) {
                int nb = (ks + 1) & 1;
                uint32_t ca = (((uint32_t)((ks + 1) * 32)) | akh) ^ aswz;
                uint32_t cb = (((uint32_t)((ks + 1) * 32)) | bkh) ^ bswz;
                LDSM4(f[nb].a0, st + aoff0 + ca);  LDSM4(f[nb].a1, st + aoff1 + ca);
                LDSM4(f[nb].b0, stB + boff0 + cb); LDSM4(f[nb].b1, stB + boff1 + cb); LDSM4(f[nb].b2, stB + boff2 + cb);
            }
            Frag& c = f[ks & 1];
            mma_f16(acc[0][0], c.a0, c.b0[0], c.b0[1]);  mma_f16(acc[1][0], c.a1, c.b0[0], c.b0[1]);
            mma_f16(acc[0][1], c.a0, c.b0[2], c.b0[3]);  mma_f16(acc[1][1], c.a1, c.b0[2], c.b0[3]);
            mma_f16(acc[0][2], c.a0, c.b1[0], c.b1[1]);  mma_f16(acc[1][2], c.a1, c.b1[0], c.b1[1]);
            mma_f16(acc[0][3], c.a0, c.b1[2], c.b1[3]);  mma_f16(acc[1][3], c.a1, c.b1[2], c.b1[3]);
            mma_f16(acc[0][4], c.a0, c.b2[0], c.b2[1]);  mma_f16(acc[1][4], c.a1, c.b2[0], c.b2[1]);
            mma_f16(acc[0][5], c.a0, c.b2[2], c.b2[3]);  mma_f16(acc[1][5], c.a1, c.b2[2], c.b2[3]);
        }
    }

    if (mode == 0) {
#pragma unroll
        for (int mt = 0; mt < 2; ++mt)
#pragma unroll
            for (int nt = 0; nt < 6; ++nt) {
                int u = m0 + wm * 32 + mt * 16 + gid;
                int n = j0 + wn * 48 + nt * 8 + tig * 2;
                float bv0 = bias[n], bv1 = bias[n + 1];
                __half2 v0 = __floats2half2_rn(acc[mt][nt][0] + bv0, acc[mt][nt][1] + bv1);
                __half2 v1 = __floats2half2_rn(acc[mt][nt][2] + bv0, acc[mt][nt][3] + bv1);
                *(__half2*)&gout[(size_t)u * NG + n]       = v0;
                *(__half2*)&gout[(size_t)(u + 8) * NG + n] = v1;
            }
    } else {
        // register-local cell: acc[mt][jh]=i, acc[mt][2+jh]=g, acc[mt][4+jh]=o
#pragma unroll
        for (int mt = 0; mt < 2; ++mt)
#pragma unroll
            for (int jh = 0; jh < 2; ++jh)
#pragma unroll
                for (int rp = 0; rp < 2; ++rp) {
                    int row = m0 + wm * 32 + mt * 16 + gid + rp * 8;
                    int nb = j0 + wn * 48 + jh * 8 + tig * 2;
                    float hv[2];
#pragma unroll
                    for (int col = 0; col < 2; ++col) {
                        float gi = acc[mt][jh][rp * 2 + col]     + bias[nb + col];
                        float gg = acc[mt][2 + jh][rp * 2 + col] + bias[nb + 16 + col];
                        float go = acc[mt][4 + jh][rp * 2 + col] + bias[nb + 32 + col];
                        hv[col] = sigm(go) * tanhe(sigm(gi) * tanhe(gg));
                    }
                    int j = bn * 32 + wn * 16 + jh * 8 + tig * 2;
                    *(float2*)&fout[(size_t)row * out_ld + j] = make_float2(hv[0], hv[1]);
                }
    }
}

// ---------------- persistent recurrence kernel ----------------
// 128 CTAs (grid 2x64), 1/SM. R9 structure (snapshot-gated fine-grained producer
// sync). G tile fetched per-row INDIRECTLY from Gu via uid_of (dedup).
__global__ __launch_bounds__(256, 1) void lstm_recur(
    const __half* __restrict__ Gu, const __half* __restrict__ W,
    __half* __restrict__ H0, __half* __restrict__ H1, float* __restrict__ out)
{
    extern __shared__ char smem[];
    const uint32_t sbase = smem_u32(smem);
    const uint32_t gsm = sbase + GEMM_SMEM;
    __half* GsmH = (__half*)(smem + GEMM_SMEM);
    const uint32_t snap_base = sbase + SNAP_OFF;
    const int* snapI = (const int*)(smem + SNAP_OFF);
    const int tid = threadIdx.x;
    const int lane = tid & 31, warp = tid >> 5;
    const int gid = lane >> 2, tig = lane & 3;
    const int wm = warp & 3, wn = warp >> 2;
    const int x = blockIdx.x, y = blockIdx.y;
    const int m0 = x * TM, j0 = y * TN;

    const int ar = wm * 32 + (lane & 15);
    const uint32_t aoff0 = (uint32_t)ar * 128u, aoff1 = aoff0 + 2048u;
    const uint32_t aswz  = (uint32_t)(ar & 7) << 4;
    const uint32_t akh   = ((lane >> 4) & 1) << 4;
    const int brb = wn * 48 + (lane & 7) + ((lane >> 4) << 3);
    const uint32_t bswz = (uint32_t)(brb & 7) << 4;
    const uint32_t bkh  = ((lane >> 3) & 1) << 4;
    const uint32_t boff0 = (uint32_t)brb * 128u, boff1 = boff0 + 2048u, boff2 = boff0 + 4096u;

    const char* Bbase = (const char*)W + (size_t)j0 * 2 * HID;

#pragma unroll 1
    for (int s = 0; s < SEQ; ++s) {
        const int t = (SEQ - 1) - s;

        // group 0: G tile (indirect rows from Gu) + (s>0) W stages 0..2
        {
            const int* uid_t = g_uid_of + t * 256 + m0;
#pragma unroll
            for (int i = 0; i < 6; ++i) {                 // 128 rows x 12 chunks = 1536
                int sl = tid + i * 256;
                int r = sl / 12, q = sl - r * 12;
                int u = __ldg(uid_t + r);
                CP16(gsm + (uint32_t)(r * GROW_B + q * 16),
                     (const char*)Gu + (size_t)u * (NG * 2) + (size_t)(j0 * 2) + q * 16);
            }
        }
        if (s > 0) {
#pragma unroll
            for (int st_ = 0; st_ < 3; ++st_) {
                uint32_t sb = sbase + (uint32_t)st_ * STAGE_BYTES + STAGE_A;
                const char* Bb = Bbase + st_ * 128;
#pragma unroll
                for (int i = 0; i < 3; ++i) {
                    int sl = tid + i * 256;
                    int row = sl >> 3, q = sl & 7;
                    CP16(sb + (uint32_t)(row * 128) + (((uint32_t)(q * 16)) ^ ((uint32_t)(row & 7) << 4)),
                         Bb + (size_t)row * 2 * HID + q * 16);
                }
            }
        }
        asm volatile("cp.async.commit_group;");

        float acc[2][6][4];
#pragma unroll
        for (int mt = 0; mt < 2; ++mt)
#pragma unroll
            for (int nt = 0; nt < 6; ++nt)
#pragma unroll
                for (int c = 0; c < 4; ++c) acc[mt][nt][c] = 0.f;

        if (s > 0) {
            const int* flg = &g_flag[s - 1][x][0];

            // gate only on producers y0..5 (needed by prologue stages 0..2)
            {
                int not_ready;
                do {
                    int v = 1;
                    if (tid < 6)
                        asm volatile("ld.acquire.gpu.global.b32 %0, [%1];"
                                     : "=r"(v) : "l"(flg + tid) : "memory");
                    not_ready = __syncthreads_count(v == 0);
                } while (not_ready != 0);
            }

            const __half* Ap = ((s + 1) & 1) ? H1 : H0;
            const char* Abase = (const char*)Ap + (size_t)m0 * 2 * HID;

            auto fillA = [&](int kt) {
                uint32_t sa = sbase + (uint32_t)(kt & 3) * STAGE_BYTES;
                const char* Ab = Abase + kt * 128;
#pragma unroll
                for (int i = 0; i < 4; ++i) {
                    int sl = tid + i * 256;
                    int row = sl >> 3, q = sl & 7;
                    CP16(sa + (uint32_t)(row * 128) + (((uint32_t)(q * 16)) ^ ((uint32_t)(row & 7) << 4)),
                         Ab + (size_t)row * 2 * HID + q * 16);
                }
            };
            auto fillB = [&](int kt) {
                uint32_t sb = sbase + (uint32_t)(kt & 3) * STAGE_BYTES + STAGE_A;
                const char* Bb = Bbase + kt * 128;
#pragma unroll
                for (int i = 0; i < 3; ++i) {
                    int sl = tid + i * 256;
                    int row = sl >> 3, q = sl & 7;
                    CP16(sb + (uint32_t)(row * 128) + (((uint32_t)(q * 16)) ^ ((uint32_t)(row & 7) << 4)),
                         Bb + (size_t)row * 2 * HID + q * 16);
                }
            };

            // A prologue: snapshot (slot (j+4)&3) + fillA(j+3), j=-3..-1
#pragma unroll
            for (int j = -3; j < 0; ++j) {
                if (tid < 16)
                    CP16(snap_base + (uint32_t)(((j + 4) & 3) * 256 + tid * 16),
                         (const char*)flg + tid * 16);
                fillA(j + 3);
                asm volatile("cp.async.commit_group;");
            }

            Frag f[2];
#pragma unroll 1
            for (int kt = 0; kt < 32; ++kt) {
                asm volatile("cp.async.wait_group 2;");
                __syncthreads();

                // ---- compute stage kt ----
                uint32_t st  = sbase + (uint32_t)(kt & 3) * STAGE_BYTES;
                uint32_t stB = st + STAGE_A;
                {
                    uint32_t ca = akh ^ aswz, cb = bkh ^ bswz;
                    LDSM4(f[0].a0, st + aoff0 + ca);  LDSM4(f[0].a1, st + aoff1 + ca);
                    LDSM4(f[0].b0, stB + boff0 + cb); LDSM4(f[0].b1, stB + boff1 + cb); LDSM4(f[0].b2, stB + boff2 + cb);
                }
#pragma unroll
                for (int ks = 0; ks < 4; ++ks) {
                    if (ks < 3) {
                        int nb = (ks + 1) & 1;
                        uint32_t ca = (((uint32_t)((ks + 1) * 32)) | akh) ^ aswz;
                        uint32_t cb = (((uint32_t)((ks + 1) * 32)) | bkh) ^ bswz;
                        LDSM4(f[nb].a0, st + aoff0 + ca);  LDSM4(f[nb].a1, st + aoff1 + ca);
                        LDSM4(f[nb].b0, stB + boff0 + cb); LDSM4(f[nb].b1, stB + boff1 + cb); LDSM4(f[nb].b2, stB + boff2 + cb);
                    }
                    Frag& c = f[ks & 1];
                    mma_f16(acc[0][0], c.a0, c.b0[0], c.b0[1]);  mma_f16(acc[1][0], c.a1, c.b0[0], c.b0[1]);
                    mma_f16(acc[0][1], c.a0, c.b0[2], c.b0[3]);  mma_f16(acc[1][1], c.a1, c.b0[2], c.b0[3]);
                    mma_f16(acc[0][2], c.a0, c.b1[0], c.b1[1]);  mma_f16(acc[1][2], c.a1, c.b1[0], c.b1[1]);
                    mma_f16(acc[0][3], c.a0, c.b1[2], c.b1[3]);  mma_f16(acc[1][3], c.a1, c.b1[2], c.b1[3]);
                    mma_f16(acc[0][4], c.a0, c.b2[0], c.b2[1]);  mma_f16(acc[1][4], c.a1, c.b2[0], c.b2[1]);
                    mma_f16(acc[0][5], c.a0, c.b2[2], c.b2[3]);  mma_f16(acc[1][5], c.a1, c.b2[2], c.b2[3]);
                }

                // ---- gate + refill stage kf = kt+3 ----
                int kf = kt + 3;
                if (kf < 32) {
                    int r0 = snapI[((kt + 1) & 3) * 64 + 2 * kf];
                    int r1 = snapI[((kt + 1) & 3) * 64 + 2 * kf + 1];
                    if (!(r0 && r1)) {                 // snapshot stale -> spin fallback
                        int not_ready;
                        do {
                            int v = 1;
                            if (tid < 2)
                                asm volatile("ld.acquire.gpu.global.b32 %0, [%1];"
                                             : "=r"(v) : "l"(flg + 2 * kf + tid) : "memory");
                            not_ready = __syncthreads_count(v == 0);
                        } while (not_ready != 0);
                    }
                    if (kt <= 25 && tid < 16)          // refresh snapshot (slot kt&3)
                        CP16(snap_base + (uint32_t)((kt & 3) * 256 + tid * 16),
                             (const char*)flg + tid * 16);
                    fillA(kf);
                    fillB(kf);
                }
                asm volatile("cp.async.commit_group;");
            }
        } else {
            asm volatile("cp.async.wait_group 0;");
            __syncthreads();
        }

        // ---- register-local cell epilogue (G addend from b-major smem tile) ----
        __half* Hout = (s & 1) ? H1 : H0;
#pragma unroll
        for (int mt = 0; mt < 2; ++mt)
#pragma unroll
            for (int jh = 0; jh < 2; ++jh)
#pragma unroll
                for (int rp = 0; rp < 2; ++rp) {
                    int rl = wm * 32 + mt * 16 + gid + rp * 8;
                    int nb = wn * 48 + jh * 8 + tig * 2;
                    float2 giF = __half22float2(*(const __half2*)&GsmH[rl * GROW_H + nb]);
                    float2 ggF = __half22float2(*(const __half2*)&GsmH[rl * GROW_H + nb + 16]);
                    float2 goF = __half22float2(*(const __half2*)&GsmH[rl * GROW_H + nb + 32]);
                    float hv[2];
#pragma unroll
                    for (int col = 0; col < 2; ++col) {
                        float gi = acc[mt][jh][rp * 2 + col]     + (col ? giF.y : giF.x);
                        float gg = acc[mt][2 + jh][rp * 2 + col] + (col ? ggF.y : ggF.x);
                        float go = acc[mt][4 + jh][rp * 2 + col] + (col ? goF.y : goF.x);
                        hv[col] = sigm(go) * tanhe(sigm(gi) * tanhe(gg));
                    }
                    int j = y * 32 + wn * 16 + jh * 8 + tig * 2;
                    int row = m0 + rl;
                    if (s < SEQ - 1) {
                        *(__half2*)&Hout[(size_t)row * HID + j] = __floats2half2_rn(hv[0], hv[1]);
                    } else {
                        *(float2*)&out[(size_t)row * (2 * HID) + HID + j] = make_float2(hv[0], hv[1]);
                    }
                }
        __syncthreads();                 // GsmH reads + stage reads complete before next prefetch
        if (tid == 0 && s < SEQ - 1) {
            __threadfence();             // publish ALL warps' H stores at gpu scope
            asm volatile("st.release.gpu.global.b32 [%0], %1;"
                         :: "l"(&g_flag[s][x][y]), "r"(1) : "memory");
        }
    }
}

// ---------------- launch ----------------
extern "C" void kernel_launch(void* const* d_in, const int* in_sizes, int n_in,
                              void* d_out, int out_size) {
    const int*   inputs = (const int*)d_in[0];
    const float* table  = (const float*)d_in[1];
    const float* Wih_f  = (const float*)d_in[2];
    // d_in[3] = W_hh_f: mathematically unused (forward h = 0)
    const float* bih_f  = (const float*)d_in[4];
    const float* bhh_f  = (const float*)d_in[5];
    const float* Wih_b  = (const float*)d_in[6];
    const float* Whh_b  = (const float*)d_in[7];
    const float* bih_b  = (const float*)d_in[8];
    const float* bhh_b  = (const float*)d_in[9];
    float* out = (float*)d_out;

    __half *Xu, *Xlast, *Gu, *Whh, *Wib, *Wif, *H;
    float *bb, *bf;
    cudaGetSymbolAddress((void**)&Xu,    g_Xu);
    cudaGetSymbolAddress((void**)&Xlast, g_Xlast);
    cudaGetSymbolAddress((void**)&Gu,    g_Gu);
    cudaGetSymbolAddress((void**)&Whh,   g_Whh);
    cudaGetSymbolAddress((void**)&Wib,   g_Wib);
    cudaGetSymbolAddress((void**)&Wif,   g_Wif);
    cudaGetSymbolAddress((void**)&bb,    g_bb);
    cudaGetSymbolAddress((void**)&bf,    g_bf);
    cudaGetSymbolAddress((void**)&H,     g_H);

    cudaFuncSetAttribute(lstm_gemm,  cudaFuncAttributeMaxDynamicSharedMemorySize, GEMM_SMEM);
    cudaFuncSetAttribute(lstm_recur, cudaFuncAttributeMaxDynamicSharedMemorySize, RECUR_SMEM);

    // dedup + prep
    reset_all<<<(VOCAB + 255) / 256, 256>>>();
    claim_tokens<<<NM / 256, 256>>>(inputs);
    map_uid<<<NM / 256, 256>>>(inputs);
    gather_unique<<<NM, 128>>>(table, Xu);
    gather_last<<<BATCH, 128>>>(inputs, table, Xlast);
    pack_weight<<<NG, 128>>>(Whh, Whh_b, HID);
    pack_weight<<<NG, 128>>>(Wib, Wih_b, EMB);
    pack_weight<<<NG, 128>>>(Wif, Wih_f, EMB);
    pack_bias<<<(NG + 255) / 256, 256>>>(bb, bih_b, bhh_b, bf, bih_f, bhh_f);

    // precompute Gu[u][n] for unique tokens only (early-exit panels beyond g_nu)
    lstm_gemm<<<dim3(NG / TN, NM / TM), 256, GEMM_SMEM>>>(
        Xu, EMB, Wib, bb, Gu, nullptr, 0, 0);

    // forward direction: single cell on last timestep, h=c=0 -> out[:, 0:2048]
    lstm_gemm<<<dim3(BATCH / TM, NG / TN), 256, GEMM_SMEM>>>(
        Xlast, EMB, Wif, bf, nullptr, out, 1, 2 * HID);

    // backward recurrence: one persistent kernel, 128 resident CTAs
    lstm_recur<<<dim3(2, 64), 256, RECUR_SMEM>>>(
        Gu, Whh, H, H + (size_t)BATCH * HID, out);
}